// round 1
// baseline (speedup 1.0000x reference)
#include <cuda_runtime.h>
#include <math.h>

#define S       64
#define LPREV   512
#define NF      193
#define NFRAMES 100
#define BATCH   64
#define NTH     256

__device__ __forceinline__ float sigm(float x) { return 1.0f / (1.0f + __expf(-x)); }

// out[row] = act( sum_i W[row,i] * vin[i] ), W row-major (out_dim, in_dim), in_dim % 4 == 0.
// 4 threads per row, 64 rows per iteration (NTH=256). act: 0 = none, 1 = tanh.
__device__ __forceinline__ void matvec(const float* __restrict__ W,
                                       const float* __restrict__ vin,
                                       float* __restrict__ vout,
                                       int out_dim, int in_dim, int act)
{
    const int t  = threadIdx.x;
    const int p  = t & 3;
    const int r0 = t >> 2;
    const int nf4 = in_dim >> 2;
    const float4* x = reinterpret_cast<const float4*>(vin);
    for (int row = r0; row < out_dim; row += (NTH / 4)) {
        const float4* w = reinterpret_cast<const float4*>(W + row * in_dim);
        float acc = 0.f;
        #pragma unroll 4
        for (int j = p; j < nf4; j += 4) {
            float4 wv = __ldg(&w[j]);
            float4 xv = x[j];
            acc = fmaf(wv.x, xv.x, acc);
            acc = fmaf(wv.y, xv.y, acc);
            acc = fmaf(wv.z, xv.z, acc);
            acc = fmaf(wv.w, xv.w, acc);
        }
        acc += __shfl_xor_sync(0xffffffffu, acc, 1);
        acc += __shfl_xor_sync(0xffffffffu, acc, 2);
        if (p == 0) {
            if (act == 1) acc = tanhf(acc);
            vout[row] = acc;
        }
    }
}

__global__ __launch_bounds__(NTH, 1)
void fargan_kernel(const float* __restrict__ feats,   // (B, 193, 100)
                   const float* __restrict__ glob,    // (B, 64)
                   const float* __restrict__ prev0,   // (B, 512)
                   const float* __restrict__ Wc1,     // (256,256)
                   const float* __restrict__ Wc2,     // (256,256)
                   const float* __restrict__ Wc3,     // (512,256)
                   const float* __restrict__ Wfw,     // (64,388)
                   const float* __restrict__ Wfw_g,   // (64,64)
                   const float* __restrict__ Wih1,    // (192,128)
                   const float* __restrict__ Whh1,    // (192,64)
                   const float* __restrict__ Wih2,
                   const float* __restrict__ Whh2,
                   const float* __restrict__ Wih3,
                   const float* __restrict__ Whh3,
                   const float* __restrict__ Wg1,     // (64,64)
                   const float* __restrict__ Wg2,
                   const float* __restrict__ Wg3,
                   const float* __restrict__ Wsg,     // (128,128)
                   const float* __restrict__ Wsd,     // (128,320)
                   const float* __restrict__ Wout,    // (64,128)
                   float* __restrict__ outp)          // (B, 25600)
{
    const int b   = blockIdx.x;
    const int tid = threadIdx.x;

    __shared__ __align__(16) float ring[LPREV];
    __shared__ __align__(16) float st1[S], st2[S], st3[S];
    __shared__ __align__(16) float sfw[2 * S];
    __shared__ __align__(16) float bufA[512];
    __shared__ __align__(16) float bufB[512];
    __shared__ __align__(16) float cbuf[512];
    __shared__ __align__(16) float subin[388];
    __shared__ __align__(16) float gi[3 * S];
    __shared__ __align__(16) float gh[3 * S];
    __shared__ __align__(16) float psub[S];
    __shared__ __align__(16) float fwv[S];
    __shared__ __align__(16) float xcat[2 * S];
    __shared__ __align__(16) float o1v[S], o2v[S], o3v[S];
    __shared__ __align__(16) float skip[5 * S];
    __shared__ __align__(16) float sdv[2 * S];
    __shared__ __align__(16) float sov[2 * S];
    __shared__ __align__(16) float gg[2 * S];
    __shared__ __align__(16) float outv[S];
    __shared__ int period_sh;

    // init state
    for (int i = tid; i < LPREV; i += NTH) ring[i] = prev0[b * LPREV + i];
    if (tid < S) { st1[tid] = 0.f; st2[tid] = 0.f; st3[tid] = 0.f; }
    for (int i = tid; i < 2 * S; i += NTH) sfw[i] = 0.f;
    int head = 0;
    __syncthreads();

    const float* fb = feats + (long)b * NF * NFRAMES;

    for (int tf = 0; tf < NFRAMES; tf++) {
        // ---- conditioning: x = concat(feat_t[:192], global) ----
        for (int f = tid; f < 192; f += NTH) bufA[f] = fb[f * NFRAMES + tf];
        for (int i = tid; i < 64; i += NTH)  bufA[192 + i] = glob[b * 64 + i];
        if (tid == 0) period_sh = (int)lrintf(fb[192 * NFRAMES + tf]);
        __syncthreads();
        matvec(Wc1, bufA, bufB, 256, 256, 1); __syncthreads();
        matvec(Wc2, bufB, bufA, 256, 256, 1); __syncthreads();
        matvec(Wc3, bufA, cbuf, 512, 256, 1); __syncthreads();
        const int period = period_sh;

        for (int k = 0; k < 4; k++) {
            // ---- build subframe input: [feat2s(128) | prev_sub(64) | lookback(68) | sfw(128)] ----
            for (int m = tid; m < 128; m += NTH) subin[m] = cbuf[4 * m + k];
            if (tid < 64) {
                float v = ring[(head + 448 + tid) & 511];
                subin[128 + tid] = v;
                psub[tid] = v;
            }
            if (tid < 68) {
                int idx = LPREV - period + tid - 2;
                if (idx >= LPREV) idx -= period;
                subin[192 + tid] = ring[(head + idx) & 511];
            }
            for (int i = tid; i < 128; i += NTH) subin[260 + i] = sfw[i];
            __syncthreads();

            // ---- fw = GLU(tanh(subin @ Wfw.T), Wfw_g) ----
            matvec(Wfw, subin, fwv, 64, 388, 1); __syncthreads();
            matvec(Wfw_g, fwv, gg, 64, 64, 0);   __syncthreads();
            if (tid < 64) {
                float f2 = fwv[tid] * sigm(gg[tid]);
                fwv[tid] = f2;
                xcat[tid] = f2;
                xcat[64 + tid] = psub[tid];
            }
            __syncthreads();

            // ---- GRU1 + GLU ----
            matvec(Wih1, xcat, gi, 192, 128, 0);
            matvec(Whh1, st1,  gh, 192, 64, 0);
            __syncthreads();
            if (tid < 64) {
                float r = sigm(gi[tid] + gh[tid]);
                float z = sigm(gi[64 + tid] + gh[64 + tid]);
                float n = tanhf(gi[128 + tid] + r * gh[128 + tid]);
                st1[tid] = (1.f - z) * n + z * st1[tid];
            }
            __syncthreads();
            matvec(Wg1, st1, gg, 64, 64, 0); __syncthreads();
            if (tid < 64) {
                float v = st1[tid] * sigm(gg[tid]);
                o1v[tid] = v;
                xcat[tid] = v;
            }
            __syncthreads();

            // ---- GRU2 + GLU ----
            matvec(Wih2, xcat, gi, 192, 128, 0);
            matvec(Whh2, st2,  gh, 192, 64, 0);
            __syncthreads();
            if (tid < 64) {
                float r = sigm(gi[tid] + gh[tid]);
                float z = sigm(gi[64 + tid] + gh[64 + tid]);
                float n = tanhf(gi[128 + tid] + r * gh[128 + tid]);
                st2[tid] = (1.f - z) * n + z * st2[tid];
            }
            __syncthreads();
            matvec(Wg2, st2, gg, 64, 64, 0); __syncthreads();
            if (tid < 64) {
                float v = st2[tid] * sigm(gg[tid]);
                o2v[tid] = v;
                xcat[tid] = v;
            }
            __syncthreads();

            // ---- GRU3 + GLU ----
            matvec(Wih3, xcat, gi, 192, 128, 0);
            matvec(Whh3, st3,  gh, 192, 64, 0);
            __syncthreads();
            if (tid < 64) {
                float r = sigm(gi[tid] + gh[tid]);
                float z = sigm(gi[64 + tid] + gh[64 + tid]);
                float n = tanhf(gi[128 + tid] + r * gh[128 + tid]);
                st3[tid] = (1.f - z) * n + z * st3[tid];
            }
            __syncthreads();
            matvec(Wg3, st3, gg, 64, 64, 0); __syncthreads();
            if (tid < 64) {
                float v = st3[tid] * sigm(gg[tid]);
                o3v[tid] = v;
                // skip = [o1, o2, o3, fw, prev_sub]
                skip[tid]       = o1v[tid];
                skip[64 + tid]  = o2v[tid];
                skip[128 + tid] = v;
                skip[192 + tid] = fwv[tid];
                skip[256 + tid] = psub[tid];
            }
            __syncthreads();

            // ---- skip head: so = GLU(tanh(skip @ Wsd.T), Wsg); out = tanh(so @ Wout.T) ----
            matvec(Wsd, skip, sdv, 128, 320, 1); __syncthreads();
            matvec(Wsg, sdv, gg, 128, 128, 0);   __syncthreads();
            if (tid < 128) sov[tid] = sdv[tid] * sigm(gg[tid]);
            __syncthreads();
            matvec(Wout, sov, outv, 64, 128, 1); __syncthreads();

            // ---- emit output, update ring (drop oldest 64, append out), update sfw ----
            if (tid < 64) {
                float v = outv[tid];
                outp[(long)b * (NFRAMES * 4 * S) + tf * (4 * S) + k * S + tid] = v;
                ring[(head + tid) & 511] = v;
            }
            for (int m = tid; m < 128; m += NTH) sfw[m] = cbuf[4 * m + k];
            head = (head + 64) & 511;
            __syncthreads();
        }
    }
}

extern "C" void kernel_launch(void* const* d_in, const int* in_sizes, int n_in,
                              void* d_out, int out_size)
{
    const float* feats = (const float*)d_in[0];
    const float* glob  = (const float*)d_in[1];
    const float* prev0 = (const float*)d_in[2];
    const float* Wc1   = (const float*)d_in[3];
    const float* Wc2   = (const float*)d_in[4];
    const float* Wc3   = (const float*)d_in[5];
    const float* Wfw   = (const float*)d_in[6];
    const float* Wfw_g = (const float*)d_in[7];
    const float* Wih1  = (const float*)d_in[8];
    const float* Whh1  = (const float*)d_in[9];
    const float* Wih2  = (const float*)d_in[10];
    const float* Whh2  = (const float*)d_in[11];
    const float* Wih3  = (const float*)d_in[12];
    const float* Whh3  = (const float*)d_in[13];
    const float* Wg1   = (const float*)d_in[14];
    const float* Wg2   = (const float*)d_in[15];
    const float* Wg3   = (const float*)d_in[16];
    const float* Wsg   = (const float*)d_in[17];
    const float* Wsd   = (const float*)d_in[18];
    const float* Wout  = (const float*)d_in[19];
    float* outp = (float*)d_out;

    fargan_kernel<<<BATCH, NTH>>>(feats, glob, prev0,
                                  Wc1, Wc2, Wc3, Wfw, Wfw_g,
                                  Wih1, Whh1, Wih2, Whh2, Wih3, Whh3,
                                  Wg1, Wg2, Wg3, Wsg, Wsd, Wout, outp);
}

// round 2
// speedup vs baseline: 1.4313x; 1.4313x over previous
#include <cuda_runtime.h>
#include <math.h>

#define S       64
#define LPREV   512
#define NF      193
#define NFRAMES 100
#define BATCH   64
#define NTH     256
#define NBT     (BATCH * NFRAMES)   // 6400

// ---------------- scratch (static device allocations) ----------------
__device__ float g_X [NBT * 256];
__device__ float g_H1[NBT * 256];
__device__ float g_H2[NBT * 256];
__device__ float g_C [NBT * 512];
__device__ int   g_period[NBT];

__device__ __forceinline__ float sigm(float x) { return 1.0f / (1.0f + __expf(-x)); }

// ---------------- conditioning precompute ----------------

__global__ void build_x_kernel(const float* __restrict__ feats,
                               const float* __restrict__ glob)
{
    const int bt = blockIdx.x;
    const int b = bt / NFRAMES, t = bt % NFRAMES;
    const float* fb = feats + (long)b * NF * NFRAMES;
    for (int i = threadIdx.x; i < 192; i += blockDim.x)
        g_X[bt * 256 + i] = fb[i * NFRAMES + t];
    for (int i = threadIdx.x; i < 64; i += blockDim.x)
        g_X[bt * 256 + 192 + i] = glob[b * 64 + i];
    if (threadIdx.x == 0)
        g_period[bt] = (int)lrintf(fb[192 * NFRAMES + t]);
}

// C[M,N] = tanh(A[M,K] @ W[N,K]^T); M=6400, K=256, N in {256,512}; tiles 64x64x64
__global__ __launch_bounds__(256)
void gemm_tanh_kernel(const float* __restrict__ Wt, int layer, int N, int K)
{
    const float* A = (layer == 0) ? g_X : (layer == 1) ? g_H1 : g_H2;
    float*       C = (layer == 0) ? g_H1 : (layer == 1) ? g_H2 : g_C;

    __shared__ float As[64][68];
    __shared__ float Ws[64][68];

    const int tid = threadIdx.x;
    const int m0 = blockIdx.y * 64, n0 = blockIdx.x * 64;
    const int lr = tid >> 2, lc = tid & 3;
    const int ty = tid >> 4, tx = tid & 15;

    float acc[4][4] = {};

    for (int k0 = 0; k0 < K; k0 += 64) {
        const float4* Arow = (const float4*)(A  + (long)(m0 + lr) * K + k0);
        const float4* Wrow = (const float4*)(Wt + (long)(n0 + lr) * K + k0);
        #pragma unroll
        for (int jj = 0; jj < 4; jj++) {
            float4 av = __ldg(&Arow[lc * 4 + jj]);
            float4 wv = __ldg(&Wrow[lc * 4 + jj]);
            int kk = lc * 16 + jj * 4;
            As[kk + 0][lr] = av.x; As[kk + 1][lr] = av.y;
            As[kk + 2][lr] = av.z; As[kk + 3][lr] = av.w;
            Ws[kk + 0][lr] = wv.x; Ws[kk + 1][lr] = wv.y;
            Ws[kk + 2][lr] = wv.z; Ws[kk + 3][lr] = wv.w;
        }
        __syncthreads();
        #pragma unroll
        for (int kk = 0; kk < 64; kk++) {
            float4 a = *(const float4*)&As[kk][ty * 4];
            float4 w = *(const float4*)&Ws[kk][tx * 4];
            acc[0][0] = fmaf(a.x, w.x, acc[0][0]); acc[0][1] = fmaf(a.x, w.y, acc[0][1]);
            acc[0][2] = fmaf(a.x, w.z, acc[0][2]); acc[0][3] = fmaf(a.x, w.w, acc[0][3]);
            acc[1][0] = fmaf(a.y, w.x, acc[1][0]); acc[1][1] = fmaf(a.y, w.y, acc[1][1]);
            acc[1][2] = fmaf(a.y, w.z, acc[1][2]); acc[1][3] = fmaf(a.y, w.w, acc[1][3]);
            acc[2][0] = fmaf(a.z, w.x, acc[2][0]); acc[2][1] = fmaf(a.z, w.y, acc[2][1]);
            acc[2][2] = fmaf(a.z, w.z, acc[2][2]); acc[2][3] = fmaf(a.z, w.w, acc[2][3]);
            acc[3][0] = fmaf(a.w, w.x, acc[3][0]); acc[3][1] = fmaf(a.w, w.y, acc[3][1]);
            acc[3][2] = fmaf(a.w, w.z, acc[3][2]); acc[3][3] = fmaf(a.w, w.w, acc[3][3]);
        }
        __syncthreads();
    }
    #pragma unroll
    for (int i = 0; i < 4; i++)
        #pragma unroll
        for (int j = 0; j < 4; j++)
            C[(long)(m0 + ty * 4 + i) * N + n0 + tx * 4 + j] = tanhf(acc[i][j]);
}

// ---------------- serial recurrence ----------------

// global-weight matvec: 4 threads/row, float4, shfl reduce. act: 0 none, 1 tanh
__device__ __forceinline__ void matvec_g(const float* __restrict__ W,
                                         const float* __restrict__ vin,
                                         float* __restrict__ vout,
                                         int out_dim, int in_dim, int act)
{
    const int t = threadIdx.x, p = t & 3, r0 = t >> 2;
    const int nf4 = in_dim >> 2;
    const float4* x = reinterpret_cast<const float4*>(vin);
    for (int row = r0; row < out_dim; row += (NTH / 4)) {
        const float4* w = reinterpret_cast<const float4*>(W + (long)row * in_dim);
        float acc = 0.f;
        #pragma unroll 4
        for (int j = p; j < nf4; j += 4) {
            float4 wv = __ldg(&w[j]);
            float4 xv = x[j];
            acc = fmaf(wv.x, xv.x, acc);
            acc = fmaf(wv.y, xv.y, acc);
            acc = fmaf(wv.z, xv.z, acc);
            acc = fmaf(wv.w, xv.w, acc);
        }
        acc += __shfl_xor_sync(0xffffffffu, acc, 1);
        acc += __shfl_xor_sync(0xffffffffu, acc, 2);
        if (p == 0) vout[row] = (act == 1) ? tanhf(acc) : acc;
    }
}

// shared-memory-weight matvec
__device__ __forceinline__ void matvec_s(const float* W,
                                         const float* __restrict__ vin,
                                         float* __restrict__ vout,
                                         int out_dim, int in_dim, int act)
{
    const int t = threadIdx.x, p = t & 3, r0 = t >> 2;
    const int nf4 = in_dim >> 2;
    const float4* x = reinterpret_cast<const float4*>(vin);
    for (int row = r0; row < out_dim; row += (NTH / 4)) {
        const float4* w = reinterpret_cast<const float4*>(W + (long)row * in_dim);
        float acc = 0.f;
        #pragma unroll 4
        for (int j = p; j < nf4; j += 4) {
            float4 wv = w[j];
            float4 xv = x[j];
            acc = fmaf(wv.x, xv.x, acc);
            acc = fmaf(wv.y, xv.y, acc);
            acc = fmaf(wv.z, xv.z, acc);
            acc = fmaf(wv.w, xv.w, acc);
        }
        acc += __shfl_xor_sync(0xffffffffu, acc, 1);
        acc += __shfl_xor_sync(0xffffffffu, acc, 2);
        if (p == 0) vout[row] = (act == 1) ? tanhf(acc) : acc;
    }
}

__device__ __forceinline__ void copy4(float* dst, const float* __restrict__ src, int n)
{
    const float4* s = (const float4*)src;
    float4* d = (float4*)dst;
    for (int i = threadIdx.x; i < (n >> 2); i += NTH) d[i] = __ldg(&s[i]);
}

#define DYN_FLOATS 53248   // Whh1..3 (3*12288) + Wg1..3 (3*4096) + Wfw_g (4096)
#define DYN_BYTES  (DYN_FLOATS * 4)

__global__ __launch_bounds__(NTH, 1)
void fargan_kernel(const float* __restrict__ prev0,
                   const float* __restrict__ Wfw,     // (64,388)
                   const float* __restrict__ Wfw_g,   // (64,64)
                   const float* __restrict__ Wih1,    // (192,128)
                   const float* __restrict__ Whh1,    // (192,64)
                   const float* __restrict__ Wih2,
                   const float* __restrict__ Whh2,
                   const float* __restrict__ Wih3,
                   const float* __restrict__ Whh3,
                   const float* __restrict__ Wg1,     // (64,64)
                   const float* __restrict__ Wg2,
                   const float* __restrict__ Wg3,
                   const float* __restrict__ Wsg,     // (128,128)
                   const float* __restrict__ Wsd,     // (128,320)
                   const float* __restrict__ Wout,    // (64,128)
                   float* __restrict__ outp)          // (B, 25600)
{
    const int b   = blockIdx.x;
    const int tid = threadIdx.x;
    const int p   = tid & 3;
    const int r0  = tid >> 2;

    extern __shared__ float dyn[];
    float* sWhh1 = dyn;
    float* sWhh2 = dyn + 12288;
    float* sWhh3 = dyn + 24576;
    float* sWg1  = dyn + 36864;
    float* sWg2  = dyn + 40960;
    float* sWg3  = dyn + 45056;
    float* sWfwg = dyn + 49152;

    __shared__ __align__(16) float ring[LPREV];
    __shared__ __align__(16) float st1[S], st2[S], st3[S];
    __shared__ __align__(16) float sfw[2 * S];
    __shared__ __align__(16) float cframe[512];
    __shared__ __align__(16) float subin[392];
    __shared__ __align__(16) float gi[3 * S];
    __shared__ __align__(16) float gh[3 * S];
    __shared__ __align__(16) float psub[S];
    __shared__ __align__(16) float fwv[S];
    __shared__ __align__(16) float xcat[2 * S];
    __shared__ __align__(16) float o1v[S], o2v[S];
    __shared__ __align__(16) float skip[5 * S];
    __shared__ __align__(16) float sdv[2 * S];
    __shared__ __align__(16) float sov[2 * S];
    __shared__ __align__(16) float gg[2 * S];
    __shared__ __align__(16) float outv[S];

    // ---- load cached weights into smem ----
    copy4(sWhh1, Whh1, 12288);
    copy4(sWhh2, Whh2, 12288);
    copy4(sWhh3, Whh3, 12288);
    copy4(sWg1,  Wg1,  4096);
    copy4(sWg2,  Wg2,  4096);
    copy4(sWg3,  Wg3,  4096);
    copy4(sWfwg, Wfw_g, 4096);

    // ---- register-cache Wsg (128x128) and Wout (64x128) in matvec layout ----
    float4 rsg[2][8], rout[8];
    {
        #pragma unroll
        for (int it = 0; it < 2; it++) {
            const float4* w = (const float4*)(Wsg + (r0 + it * 64) * 128);
            #pragma unroll
            for (int jj = 0; jj < 8; jj++) rsg[it][jj] = __ldg(&w[p + jj * 4]);
        }
        const float4* w = (const float4*)(Wout + r0 * 128);
        #pragma unroll
        for (int jj = 0; jj < 8; jj++) rout[jj] = __ldg(&w[p + jj * 4]);
    }

    // ---- init state ----
    for (int i = tid; i < LPREV; i += NTH) ring[i] = prev0[b * LPREV + i];
    if (tid < S) { st1[tid] = 0.f; st2[tid] = 0.f; st3[tid] = 0.f; }
    for (int i = tid; i < 2 * S; i += NTH) sfw[i] = 0.f;
    int head = 0;
    __syncthreads();

    for (int tf = 0; tf < NFRAMES; tf++) {
        const int bt = b * NFRAMES + tf;
        // conditioning row precomputed
        copy4(cframe, g_C + (long)bt * 512, 512);
        __syncthreads();
        const int period = g_period[bt];

        for (int k = 0; k < 4; k++) {
            // ---- subframe input: [feat2s(128) | prev_sub(64) | lookback(68) | sfw(128)]
            for (int m = tid; m < 128; m += NTH) subin[m] = cframe[4 * m + k];
            if (tid < 64) {
                float v = ring[(head + 448 + tid) & 511];
                subin[128 + tid] = v;
                psub[tid] = v;
            }
            if (tid < 68) {
                int idx = LPREV - period + tid - 2;
                if (idx >= LPREV) idx -= period;
                subin[192 + tid] = ring[(head + idx) & 511];
            }
            for (int i = tid; i < 128; i += NTH) subin[260 + i] = sfw[i];
            __syncthreads();

            // ---- fw = GLU(tanh(subin @ Wfw.T), Wfw_g)
            matvec_g(Wfw, subin, fwv, 64, 388, 1); __syncthreads();
            matvec_s(sWfwg, fwv, gg, 64, 64, 0);   __syncthreads();
            if (tid < 64) {
                float f2 = fwv[tid] * sigm(gg[tid]);
                fwv[tid] = f2;
                xcat[tid] = f2;
                xcat[64 + tid] = psub[tid];
            }
            __syncthreads();

            // ---- GRU1 + GLU
            matvec_g(Wih1, xcat, gi, 192, 128, 0);
            matvec_s(sWhh1, st1, gh, 192, 64, 0);
            __syncthreads();
            if (tid < 64) {
                float r = sigm(gi[tid] + gh[tid]);
                float z = sigm(gi[64 + tid] + gh[64 + tid]);
                float n = tanhf(gi[128 + tid] + r * gh[128 + tid]);
                st1[tid] = (1.f - z) * n + z * st1[tid];
            }
            __syncthreads();
            matvec_s(sWg1, st1, gg, 64, 64, 0); __syncthreads();
            if (tid < 64) {
                float v = st1[tid] * sigm(gg[tid]);
                o1v[tid] = v;
                xcat[tid] = v;
            }
            __syncthreads();

            // ---- GRU2 + GLU
            matvec_g(Wih2, xcat, gi, 192, 128, 0);
            matvec_s(sWhh2, st2, gh, 192, 64, 0);
            __syncthreads();
            if (tid < 64) {
                float r = sigm(gi[tid] + gh[tid]);
                float z = sigm(gi[64 + tid] + gh[64 + tid]);
                float n = tanhf(gi[128 + tid] + r * gh[128 + tid]);
                st2[tid] = (1.f - z) * n + z * st2[tid];
            }
            __syncthreads();
            matvec_s(sWg2, st2, gg, 64, 64, 0); __syncthreads();
            if (tid < 64) {
                float v = st2[tid] * sigm(gg[tid]);
                o2v[tid] = v;
                xcat[tid] = v;
            }
            __syncthreads();

            // ---- GRU3 + GLU
            matvec_g(Wih3, xcat, gi, 192, 128, 0);
            matvec_s(sWhh3, st3, gh, 192, 64, 0);
            __syncthreads();
            if (tid < 64) {
                float r = sigm(gi[tid] + gh[tid]);
                float z = sigm(gi[64 + tid] + gh[64 + tid]);
                float n = tanhf(gi[128 + tid] + r * gh[128 + tid]);
                st3[tid] = (1.f - z) * n + z * st3[tid];
            }
            __syncthreads();
            matvec_s(sWg3, st3, gg, 64, 64, 0); __syncthreads();
            if (tid < 64) {
                float v = st3[tid] * sigm(gg[tid]);
                skip[tid]       = o1v[tid];
                skip[64 + tid]  = o2v[tid];
                skip[128 + tid] = v;
                skip[192 + tid] = fwv[tid];
                skip[256 + tid] = psub[tid];
            }
            __syncthreads();

            // ---- skip head
            matvec_g(Wsd, skip, sdv, 128, 320, 1); __syncthreads();
            // gg = sdv @ Wsg.T (register weights)
            {
                const float4* x = (const float4*)sdv;
                #pragma unroll
                for (int it = 0; it < 2; it++) {
                    float acc = 0.f;
                    #pragma unroll
                    for (int jj = 0; jj < 8; jj++) {
                        float4 wv = rsg[it][jj];
                        float4 xv = x[p + jj * 4];
                        acc = fmaf(wv.x, xv.x, acc);
                        acc = fmaf(wv.y, xv.y, acc);
                        acc = fmaf(wv.z, xv.z, acc);
                        acc = fmaf(wv.w, xv.w, acc);
                    }
                    acc += __shfl_xor_sync(0xffffffffu, acc, 1);
                    acc += __shfl_xor_sync(0xffffffffu, acc, 2);
                    if (p == 0) gg[r0 + it * 64] = acc;
                }
            }
            __syncthreads();
            if (tid < 128) sov[tid] = sdv[tid] * sigm(gg[tid]);
            __syncthreads();
            // outv = tanh(sov @ Wout.T) (register weights)
            {
                const float4* x = (const float4*)sov;
                float acc = 0.f;
                #pragma unroll
                for (int jj = 0; jj < 8; jj++) {
                    float4 wv = rout[jj];
                    float4 xv = x[p + jj * 4];
                    acc = fmaf(wv.x, xv.x, acc);
                    acc = fmaf(wv.y, xv.y, acc);
                    acc = fmaf(wv.z, xv.z, acc);
                    acc = fmaf(wv.w, xv.w, acc);
                }
                acc += __shfl_xor_sync(0xffffffffu, acc, 1);
                acc += __shfl_xor_sync(0xffffffffu, acc, 2);
                if (p == 0) outv[r0] = tanhf(acc);
            }
            __syncthreads();

            // ---- emit, update ring + sfw
            if (tid < 64) {
                float v = outv[tid];
                outp[(long)b * (NFRAMES * 4 * S) + tf * (4 * S) + k * S + tid] = v;
                ring[(head + tid) & 511] = v;
            }
            for (int m = tid; m < 128; m += NTH) sfw[m] = cframe[4 * m + k];
            head = (head + 64) & 511;
            __syncthreads();
        }
    }
}

extern "C" void kernel_launch(void* const* d_in, const int* in_sizes, int n_in,
                              void* d_out, int out_size)
{
    const float* feats = (const float*)d_in[0];
    const float* glob  = (const float*)d_in[1];
    const float* prev0 = (const float*)d_in[2];
    const float* Wc1   = (const float*)d_in[3];
    const float* Wc2   = (const float*)d_in[4];
    const float* Wc3   = (const float*)d_in[5];
    const float* Wfw   = (const float*)d_in[6];
    const float* Wfw_g = (const float*)d_in[7];
    const float* Wih1  = (const float*)d_in[8];
    const float* Whh1  = (const float*)d_in[9];
    const float* Wih2  = (const float*)d_in[10];
    const float* Whh2  = (const float*)d_in[11];
    const float* Wih3  = (const float*)d_in[12];
    const float* Whh3  = (const float*)d_in[13];
    const float* Wg1   = (const float*)d_in[14];
    const float* Wg2   = (const float*)d_in[15];
    const float* Wg3   = (const float*)d_in[16];
    const float* Wsg   = (const float*)d_in[17];
    const float* Wsd   = (const float*)d_in[18];
    const float* Wout  = (const float*)d_in[19];
    float* outp = (float*)d_out;

    static bool attr_set = false;
    if (!attr_set) {
        cudaFuncSetAttribute(fargan_kernel,
                             cudaFuncAttributeMaxDynamicSharedMemorySize, DYN_BYTES);
        attr_set = true;
    }

    build_x_kernel<<<NBT, 64>>>(feats, glob);
    gemm_tanh_kernel<<<dim3(4, 100), 256>>>(Wc1, 0, 256, 256);
    gemm_tanh_kernel<<<dim3(4, 100), 256>>>(Wc2, 1, 256, 256);
    gemm_tanh_kernel<<<dim3(8, 100), 256>>>(Wc3, 2, 512, 256);
    fargan_kernel<<<BATCH, NTH, DYN_BYTES>>>(prev0,
                                  Wfw, Wfw_g,
                                  Wih1, Whh1, Wih2, Whh2, Wih3, Whh3,
                                  Wg1, Wg2, Wg3, Wsg, Wsd, Wout, outp);
}